// round 1
// baseline (speedup 1.0000x reference)
#include <cuda_runtime.h>

// Scratch (no cudaMalloc allowed)
#define N_NODES_MAX 1000000
__device__ float g_h[N_NODES_MAX];
__device__ float g_neigh[N_NODES_MAX];

// ---------------------------------------------------------------------------
// Zero the neighbor-accumulation buffer (float4 vectorized; N divisible by 4)
// ---------------------------------------------------------------------------
__global__ void zero_kernel(float* __restrict__ buf, int n4) {
    int i = blockIdx.x * blockDim.x + threadIdx.x;
    if (i < n4) {
        ((float4*)buf)[i] = make_float4(0.f, 0.f, 0.f, 0.f);
    }
}

// ---------------------------------------------------------------------------
// Scatter: neigh[dst[e]] += h[src[e]] for all edges. 4 edges per thread via
// int4 index loads (128-bit LDG). atomicAdd result unused -> REDG.
// ---------------------------------------------------------------------------
__global__ void scatter_kernel(const int* __restrict__ src,
                               const int* __restrict__ dst,
                               const float* __restrict__ h,
                               float* __restrict__ neigh,
                               int ne4) {
    int i = blockIdx.x * blockDim.x + threadIdx.x;
    if (i >= ne4) return;
    int4 s = ((const int4*)src)[i];
    int4 d = ((const int4*)dst)[i];
    float v0 = __ldg(&h[s.x]);
    float v1 = __ldg(&h[s.y]);
    float v2 = __ldg(&h[s.z]);
    float v3 = __ldg(&h[s.w]);
    atomicAdd(&neigh[d.x], v0);
    atomicAdd(&neigh[d.y], v1);
    atomicAdd(&neigh[d.z], v2);
    atomicAdd(&neigh[d.w], v3);
}

// ---------------------------------------------------------------------------
// Combine: out[i] = h[i]*ws + neigh[i]*wn  (scalar weights read from device)
// ---------------------------------------------------------------------------
__global__ void combine_kernel(const float* __restrict__ h,
                               const float* __restrict__ neigh,
                               const float* __restrict__ w_self,
                               const float* __restrict__ w_neigh,
                               int hop,
                               float* __restrict__ out,
                               int n4) {
    int i = blockIdx.x * blockDim.x + threadIdx.x;
    if (i >= n4) return;
    float ws = __ldg(&w_self[hop]);   // w_self[hop,0,0]
    float wn = __ldg(&w_neigh[hop]);
    float4 hv = ((const float4*)h)[i];
    float4 nv = ((const float4*)neigh)[i];
    float4 o;
    o.x = hv.x * ws + nv.x * wn;
    o.y = hv.y * ws + nv.y * wn;
    o.z = hv.z * ws + nv.z * wn;
    o.w = hv.w * ws + nv.w * wn;
    ((float4*)out)[i] = o;
}

extern "C" void kernel_launch(void* const* d_in, const int* in_sizes, int n_in,
                              void* d_out, int out_size) {
    const float* h_in    = (const float*)d_in[0];   // [N,1] f32
    const int*   src     = (const int*)d_in[1];     // [E] i32
    const int*   dst     = (const int*)d_in[2];     // [E] i32
    const float* w_self  = (const float*)d_in[3];   // [HOP,1,1]
    const float* w_neigh = (const float*)d_in[4];   // [HOP,1,1]
    float*       out     = (float*)d_out;

    const int n  = in_sizes[0];      // 1,000,000
    const int ne = in_sizes[1];      // 32,000,000
    const int num_hop = in_sizes[3]; // 3

    float* gh;
    float* gn;
    cudaGetSymbolAddress((void**)&gh, g_h);
    cudaGetSymbolAddress((void**)&gn, g_neigh);

    const int n4  = n / 4;
    const int ne4 = ne / 4;
    const int TB = 256;
    dim3 gz((n4 + TB - 1) / TB);
    dim3 gs((ne4 + TB - 1) / TB);

    for (int hop = 0; hop < num_hop; hop++) {
        const float* hcur = (hop == 0) ? h_in : gh;
        float* hout = (hop == num_hop - 1) ? out : gh;

        zero_kernel<<<gz, TB>>>(gn, n4);
        scatter_kernel<<<gs, TB>>>(src, dst, hcur, gn, ne4);
        combine_kernel<<<gz, TB>>>(hcur, gn, w_self, w_neigh, hop, hout, n4);
    }
}

// round 2
// speedup vs baseline: 1.0019x; 1.0019x over previous
#include <cuda_runtime.h>

// Scratch (no cudaMalloc allowed)
#define N_NODES_MAX 1000000
__device__ float g_h[N_NODES_MAX];
__device__ float g_neigh[N_NODES_MAX];

// ---------------------------------------------------------------------------
// Zero the neighbor-accumulation buffer (float4 vectorized; N divisible by 4)
// ---------------------------------------------------------------------------
__global__ void zero_kernel(float* __restrict__ buf, int n4) {
    int i = blockIdx.x * blockDim.x + threadIdx.x;
    if (i < n4) {
        ((float4*)buf)[i] = make_float4(0.f, 0.f, 0.f, 0.f);
    }
}

// ---------------------------------------------------------------------------
// Scatter: neigh[dst[e]] += h[src[e]] for all edges. 4 edges per thread via
// int4 index loads (128-bit LDG). atomicAdd result unused -> REDG.
// ---------------------------------------------------------------------------
__global__ void scatter_kernel(const int* __restrict__ src,
                               const int* __restrict__ dst,
                               const float* __restrict__ h,
                               float* __restrict__ neigh,
                               int ne4) {
    int i = blockIdx.x * blockDim.x + threadIdx.x;
    if (i >= ne4) return;
    int4 s = ((const int4*)src)[i];
    int4 d = ((const int4*)dst)[i];
    float v0 = __ldg(&h[s.x]);
    float v1 = __ldg(&h[s.y]);
    float v2 = __ldg(&h[s.z]);
    float v3 = __ldg(&h[s.w]);
    atomicAdd(&neigh[d.x], v0);
    atomicAdd(&neigh[d.y], v1);
    atomicAdd(&neigh[d.z], v2);
    atomicAdd(&neigh[d.w], v3);
}

// ---------------------------------------------------------------------------
// Combine: out[i] = h[i]*ws + neigh[i]*wn  (scalar weights read from device)
// ---------------------------------------------------------------------------
__global__ void combine_kernel(const float* __restrict__ h,
                               const float* __restrict__ neigh,
                               const float* __restrict__ w_self,
                               const float* __restrict__ w_neigh,
                               int hop,
                               float* __restrict__ out,
                               int n4) {
    int i = blockIdx.x * blockDim.x + threadIdx.x;
    if (i >= n4) return;
    float ws = __ldg(&w_self[hop]);   // w_self[hop,0,0]
    float wn = __ldg(&w_neigh[hop]);
    float4 hv = ((const float4*)h)[i];
    float4 nv = ((const float4*)neigh)[i];
    float4 o;
    o.x = hv.x * ws + nv.x * wn;
    o.y = hv.y * ws + nv.y * wn;
    o.z = hv.z * ws + nv.z * wn;
    o.w = hv.w * ws + nv.w * wn;
    ((float4*)out)[i] = o;
}

extern "C" void kernel_launch(void* const* d_in, const int* in_sizes, int n_in,
                              void* d_out, int out_size) {
    const float* h_in    = (const float*)d_in[0];   // [N,1] f32
    const int*   src     = (const int*)d_in[1];     // [E] i32
    const int*   dst     = (const int*)d_in[2];     // [E] i32
    const float* w_self  = (const float*)d_in[3];   // [HOP,1,1]
    const float* w_neigh = (const float*)d_in[4];   // [HOP,1,1]
    float*       out     = (float*)d_out;

    const int n  = in_sizes[0];      // 1,000,000
    const int ne = in_sizes[1];      // 32,000,000
    const int num_hop = in_sizes[3]; // 3

    float* gh;
    float* gn;
    cudaGetSymbolAddress((void**)&gh, g_h);
    cudaGetSymbolAddress((void**)&gn, g_neigh);

    const int n4  = n / 4;
    const int ne4 = ne / 4;
    const int TB = 256;
    dim3 gz((n4 + TB - 1) / TB);
    dim3 gs((ne4 + TB - 1) / TB);

    for (int hop = 0; hop < num_hop; hop++) {
        const float* hcur = (hop == 0) ? h_in : gh;
        float* hout = (hop == num_hop - 1) ? out : gh;

        zero_kernel<<<gz, TB>>>(gn, n4);
        scatter_kernel<<<gs, TB>>>(src, dst, hcur, gn, ne4);
        combine_kernel<<<gz, TB>>>(hcur, gn, w_self, w_neigh, hop, hout, n4);
    }
}

// round 3
// speedup vs baseline: 1.0051x; 1.0032x over previous
#include <cuda_runtime.h>

// Scratch (no cudaMalloc allowed)
#define N_NODES_MAX 1000000
__device__ float g_h[N_NODES_MAX];
__device__ float g_neigh[N_NODES_MAX];

// ---------------------------------------------------------------------------
// Zero the neighbor-accumulation buffer (float4 vectorized; N divisible by 4)
// ---------------------------------------------------------------------------
__global__ void zero_kernel(float* __restrict__ buf, int n4) {
    int i = blockIdx.x * blockDim.x + threadIdx.x;
    if (i < n4) {
        ((float4*)buf)[i] = make_float4(0.f, 0.f, 0.f, 0.f);
    }
}

// ---------------------------------------------------------------------------
// Scatter: neigh[dst[e]] += h[src[e]] for all edges. 4 edges per thread via
// int4 index loads (128-bit LDG). atomicAdd result unused -> REDG.
// ---------------------------------------------------------------------------
__global__ void scatter_kernel(const int* __restrict__ src,
                               const int* __restrict__ dst,
                               const float* __restrict__ h,
                               float* __restrict__ neigh,
                               int ne4) {
    int i = blockIdx.x * blockDim.x + threadIdx.x;
    if (i >= ne4) return;
    int4 s = ((const int4*)src)[i];
    int4 d = ((const int4*)dst)[i];
    float v0 = __ldg(&h[s.x]);
    float v1 = __ldg(&h[s.y]);
    float v2 = __ldg(&h[s.z]);
    float v3 = __ldg(&h[s.w]);
    atomicAdd(&neigh[d.x], v0);
    atomicAdd(&neigh[d.y], v1);
    atomicAdd(&neigh[d.z], v2);
    atomicAdd(&neigh[d.w], v3);
}

// ---------------------------------------------------------------------------
// Combine: out[i] = h[i]*ws + neigh[i]*wn  (scalar weights read from device)
// ---------------------------------------------------------------------------
__global__ void combine_kernel(const float* __restrict__ h,
                               const float* __restrict__ neigh,
                               const float* __restrict__ w_self,
                               const float* __restrict__ w_neigh,
                               int hop,
                               float* __restrict__ out,
                               int n4) {
    int i = blockIdx.x * blockDim.x + threadIdx.x;
    if (i >= n4) return;
    float ws = __ldg(&w_self[hop]);   // w_self[hop,0,0]
    float wn = __ldg(&w_neigh[hop]);
    float4 hv = ((const float4*)h)[i];
    float4 nv = ((const float4*)neigh)[i];
    float4 o;
    o.x = hv.x * ws + nv.x * wn;
    o.y = hv.y * ws + nv.y * wn;
    o.z = hv.z * ws + nv.z * wn;
    o.w = hv.w * ws + nv.w * wn;
    ((float4*)out)[i] = o;
}

extern "C" void kernel_launch(void* const* d_in, const int* in_sizes, int n_in,
                              void* d_out, int out_size) {
    const float* h_in    = (const float*)d_in[0];   // [N,1] f32
    const int*   src     = (const int*)d_in[1];     // [E] i32
    const int*   dst     = (const int*)d_in[2];     // [E] i32
    const float* w_self  = (const float*)d_in[3];   // [HOP,1,1]
    const float* w_neigh = (const float*)d_in[4];   // [HOP,1,1]
    float*       out     = (float*)d_out;

    const int n  = in_sizes[0];      // 1,000,000
    const int ne = in_sizes[1];      // 32,000,000
    const int num_hop = in_sizes[3]; // 3

    float* gh;
    float* gn;
    cudaGetSymbolAddress((void**)&gh, g_h);
    cudaGetSymbolAddress((void**)&gn, g_neigh);

    const int n4  = n / 4;
    const int ne4 = ne / 4;
    const int TB = 256;
    dim3 gz((n4 + TB - 1) / TB);
    dim3 gs((ne4 + TB - 1) / TB);

    for (int hop = 0; hop < num_hop; hop++) {
        const float* hcur = (hop == 0) ? h_in : gh;
        float* hout = (hop == num_hop - 1) ? out : gh;

        zero_kernel<<<gz, TB>>>(gn, n4);
        scatter_kernel<<<gs, TB>>>(src, dst, hcur, gn, ne4);
        combine_kernel<<<gz, TB>>>(hcur, gn, w_self, w_neigh, hop, hout, n4);
    }
}